// round 9
// baseline (speedup 1.0000x reference)
#include <cuda_runtime.h>
#include <cstdint>

#define NCLS   10
#define BLOCK  256
#define NGRID  (152 * 4)     // 4 blocks/SM -> exactly one wave
#define NWARPS (BLOCK / 32)

typedef unsigned long long ull;

__device__ float2       g_part[NGRID][NCLS];
__device__ unsigned int g_ticket = 0;

#define PACKED_ONES 0x3F8000003F800000ull   // {1.0f, 1.0f}

// One element -> 10 register accumulators.
// validity folded into inc ({0,0} no-op for masked pixels); 10 INDEPENDENT
// predicate regs so the 13-cyc pred->guard latencies overlap across classes.
__device__ __forceinline__ void acc_el(float o, float t, int m, ull* a, ull ones) {
    float e  = o - t;
    float sq = e * e;
    bool  v  = (m == 1);
    float sqv  = v ? sq   : 0.0f;
    float onev = v ? 1.0f : 0.0f;
    ull inc;
    asm("mov.b64 %0, {%1, %2};" : "=l"(inc) : "f"(sqv), "f"(onev));
    asm volatile(
        "{\n\t"
        ".reg .pred q0,q1,q2,q3,q4,q5,q6,q7,q8,q9;\n\t"
        "setp.eq.f32 q0, %10, 0F00000000;\n\t"
        "setp.eq.f32 q1, %10, 0F3F800000;\n\t"
        "setp.eq.f32 q2, %10, 0F40000000;\n\t"
        "setp.eq.f32 q3, %10, 0F40400000;\n\t"
        "setp.eq.f32 q4, %10, 0F40800000;\n\t"
        "setp.eq.f32 q5, %10, 0F40A00000;\n\t"
        "setp.eq.f32 q6, %10, 0F40C00000;\n\t"
        "setp.eq.f32 q7, %10, 0F40E00000;\n\t"
        "setp.eq.f32 q8, %10, 0F41000000;\n\t"
        "setp.eq.f32 q9, %10, 0F41100000;\n\t"
        "@q0 fma.rn.f32x2 %0, %11, %12, %0;\n\t"
        "@q1 fma.rn.f32x2 %1, %11, %12, %1;\n\t"
        "@q2 fma.rn.f32x2 %2, %11, %12, %2;\n\t"
        "@q3 fma.rn.f32x2 %3, %11, %12, %3;\n\t"
        "@q4 fma.rn.f32x2 %4, %11, %12, %4;\n\t"
        "@q5 fma.rn.f32x2 %5, %11, %12, %5;\n\t"
        "@q6 fma.rn.f32x2 %6, %11, %12, %6;\n\t"
        "@q7 fma.rn.f32x2 %7, %11, %12, %7;\n\t"
        "@q8 fma.rn.f32x2 %8, %11, %12, %8;\n\t"
        "@q9 fma.rn.f32x2 %9, %11, %12, %9;\n\t"
        "}"
        : "+l"(a[0]), "+l"(a[1]), "+l"(a[2]), "+l"(a[3]), "+l"(a[4]),
          "+l"(a[5]), "+l"(a[6]), "+l"(a[7]), "+l"(a[8]), "+l"(a[9])
        : "f"(t), "l"(inc), "l"(ones));
}

__global__ __launch_bounds__(BLOCK, 4) void loss_k(
    const float* __restrict__ outs,
    const float* __restrict__ tgts,
    const int*   __restrict__ mask,
    int n, float* __restrict__ out, int out_size)
{
    __shared__ float2 s_warp[NWARPS][NCLS];
    __shared__ float  le[NCLS];
    __shared__ unsigned int s_ticket;
    const int tid  = threadIdx.x;
    const int lane = tid & 31;
    const int wid  = tid >> 5;
    const ull ones = PACKED_ONES;

    ull acc[NCLS];
    #pragma unroll
    for (int c = 0; c < NCLS; c++) acc[c] = 0ull;

    const int n4 = n >> 2;
    const float4* __restrict__ o4 = reinterpret_cast<const float4*>(outs);
    const float4* __restrict__ t4 = reinterpret_cast<const float4*>(tgts);
    const int4*   __restrict__ m4 = reinterpret_cast<const int4*>(mask);

    const int stride = NGRID * BLOCK;
    int i = blockIdx.x * BLOCK + tid;

    for (; i + stride < n4; i += 2 * stride) {
        float4 ov0 = o4[i];
        float4 ov1 = o4[i + stride];
        float4 tv0 = t4[i];
        float4 tv1 = t4[i + stride];
        int4   mv0 = m4[i];
        int4   mv1 = m4[i + stride];
        acc_el(ov0.x, tv0.x, mv0.x, acc, ones);
        acc_el(ov0.y, tv0.y, mv0.y, acc, ones);
        acc_el(ov0.z, tv0.z, mv0.z, acc, ones);
        acc_el(ov0.w, tv0.w, mv0.w, acc, ones);
        acc_el(ov1.x, tv1.x, mv1.x, acc, ones);
        acc_el(ov1.y, tv1.y, mv1.y, acc, ones);
        acc_el(ov1.z, tv1.z, mv1.z, acc, ones);
        acc_el(ov1.w, tv1.w, mv1.w, acc, ones);
    }
    if (i < n4) {
        float4 ov = o4[i];
        float4 tv = t4[i];
        int4   mv = m4[i];
        acc_el(ov.x, tv.x, mv.x, acc, ones);
        acc_el(ov.y, tv.y, mv.y, acc, ones);
        acc_el(ov.z, tv.z, mv.z, acc, ones);
        acc_el(ov.w, tv.w, mv.w, acc, ones);
    }
    if (blockIdx.x == 0) {               // scalar tail (n % 4)
        int j = (n4 << 2) + tid;
        if (j < n) acc_el(outs[j], tgts[j], mask[j], acc, ones);
    }

    // ---- warp shuffle reduction (float2 packed in ull) ----
    #pragma unroll
    for (int off = 16; off > 0; off >>= 1) {
        #pragma unroll
        for (int c = 0; c < NCLS; c++) {
            ull other = __shfl_down_sync(0xffffffffu, acc[c], off);
            asm("fma.rn.f32x2 %0, %1, %2, %0;" : "+l"(acc[c]) : "l"(other), "l"(ones));
        }
    }
    if (lane == 0) {
        #pragma unroll
        for (int c = 0; c < NCLS; c++) {
            float2 v;
            asm("mov.b64 {%0, %1}, %2;" : "=f"(v.x), "=f"(v.y) : "l"(acc[c]));
            s_warp[wid][c] = v;
        }
    }
    __syncthreads();

    if (tid < NCLS) {
        float2 p = make_float2(0.0f, 0.0f);
        #pragma unroll
        for (int w = 0; w < NWARPS; w++) {
            float2 v = s_warp[w][tid];
            p.x += v.x; p.y += v.y;
        }
        g_part[blockIdx.x][tid] = p;
    }
    __threadfence();
    __syncthreads();
    if (tid == 0) s_ticket = atomicAdd(&g_ticket, 1u);
    __syncthreads();
    if (s_ticket != (unsigned)(gridDim.x - 1)) return;

    // ---- last block: reduce partials, finalize, write output ----
    __threadfence();

    float2 racc[NCLS];
    #pragma unroll
    for (int c = 0; c < NCLS; c++) racc[c] = make_float2(0.0f, 0.0f);
    for (int j = tid; j < NGRID; j += BLOCK) {
        #pragma unroll
        for (int c = 0; c < NCLS; c++) {
            float2 p = g_part[j][c];
            racc[c].x += p.x;
            racc[c].y += p.y;
        }
    }
    #pragma unroll
    for (int off = 16; off > 0; off >>= 1) {
        #pragma unroll
        for (int c = 0; c < NCLS; c++) {
            racc[c].x += __shfl_down_sync(0xffffffffu, racc[c].x, off);
            racc[c].y += __shfl_down_sync(0xffffffffu, racc[c].y, off);
        }
    }
    if (lane == 0) {
        #pragma unroll
        for (int c = 0; c < NCLS; c++) s_warp[wid][c] = racc[c];
    }
    __syncthreads();

    if (tid < NCLS) {
        float2 tot = make_float2(0.0f, 0.0f);
        #pragma unroll
        for (int w = 0; w < NWARPS; w++) {
            float2 v = s_warp[w][tid];
            tot.x += v.x; tot.y += v.y;
        }
        s_warp[0][tid] = tot;
        le[tid] = (tot.y > 0.0f) ? (tot.x / fmaxf(tot.y, 1.0f)) : 0.0f;
    }
    __syncthreads();

    if (tid == 0) {
        float loss = 0.0f;
        #pragma unroll
        for (int c = 0; c < NCLS; c++) loss += 0.1f * le[c];
        out[0] = loss;
        g_ticket = 0;
    } else if (tid >= 1 && tid <= NCLS) {
        out[tid] = le[tid - 1];                  // loss_each
    } else if (tid >= NCLS + 1 && tid <= 2 * NCLS) {
        out[tid] = s_warp[0][tid - NCLS - 1].y;  // class_n
    } else if (tid < out_size) {
        out[tid] = 0.0f;
    }
}

extern "C" void kernel_launch(void* const* d_in, const int* in_sizes, int n_in,
                              void* d_out, int out_size) {
    const float* outs = (const float*)d_in[0];
    const float* tgts = (const float*)d_in[1];
    const int*   mask = (const int*)d_in[2];
    float* out = (float*)d_out;
    int n = in_sizes[0];

    loss_k<<<NGRID, BLOCK>>>(outs, tgts, mask, n, out, out_size);
}

// round 10
// speedup vs baseline: 1.0007x; 1.0007x over previous
#include <cuda_runtime.h>
#include <cstdint>

#define NCLS   10
#define BLOCK  256
#define NGRID  (152 * 4)     // 4 blocks/SM -> exactly one wave
#define NWARPS (BLOCK / 32)

typedef unsigned long long ull;

__device__ float2       g_part[NGRID][NCLS];
__device__ unsigned int g_ticket = 0;

#define PACKED_ONES 0x3F8000003F800000ull   // {1.0f, 1.0f}

// One element -> 10 register accumulators (R8 body: empirically fastest).
// Guards: FSETP.EQ.AND on float target, validity folded; payload: FFMA2.
__device__ __forceinline__ void acc_el(float o, float t, int m, ull* a, ull ones) {
    float e  = o - t;
    float sq = e * e;
    asm volatile(
        "{\n\t"
        ".reg .pred pv, p;\n\t"
        ".reg .b64  inc;\n\t"
        "setp.eq.s32 pv, %12, 1;\n\t"
        "mov.b64 inc, {%10, %11};\n\t"
        "setp.eq.and.f32 p, %13, 0F00000000, pv;\n\t @p fma.rn.f32x2 %0, inc, %14, %0;\n\t"
        "setp.eq.and.f32 p, %13, 0F3F800000, pv;\n\t @p fma.rn.f32x2 %1, inc, %14, %1;\n\t"
        "setp.eq.and.f32 p, %13, 0F40000000, pv;\n\t @p fma.rn.f32x2 %2, inc, %14, %2;\n\t"
        "setp.eq.and.f32 p, %13, 0F40400000, pv;\n\t @p fma.rn.f32x2 %3, inc, %14, %3;\n\t"
        "setp.eq.and.f32 p, %13, 0F40800000, pv;\n\t @p fma.rn.f32x2 %4, inc, %14, %4;\n\t"
        "setp.eq.and.f32 p, %13, 0F40A00000, pv;\n\t @p fma.rn.f32x2 %5, inc, %14, %5;\n\t"
        "setp.eq.and.f32 p, %13, 0F40C00000, pv;\n\t @p fma.rn.f32x2 %6, inc, %14, %6;\n\t"
        "setp.eq.and.f32 p, %13, 0F40E00000, pv;\n\t @p fma.rn.f32x2 %7, inc, %14, %7;\n\t"
        "setp.eq.and.f32 p, %13, 0F41000000, pv;\n\t @p fma.rn.f32x2 %8, inc, %14, %8;\n\t"
        "setp.eq.and.f32 p, %13, 0F41100000, pv;\n\t @p fma.rn.f32x2 %9, inc, %14, %9;\n\t"
        "}"
        : "+l"(a[0]), "+l"(a[1]), "+l"(a[2]), "+l"(a[3]), "+l"(a[4]),
          "+l"(a[5]), "+l"(a[6]), "+l"(a[7]), "+l"(a[8]), "+l"(a[9])
        : "f"(sq), "f"(1.0f), "r"(m), "f"(t), "l"(ones));
}

__global__ __launch_bounds__(BLOCK, 4) void loss_k(
    const float* __restrict__ outs,
    const float* __restrict__ tgts,
    const int*   __restrict__ mask,
    int n, float* __restrict__ out, int out_size)
{
    __shared__ float2 s_warp[NWARPS][NCLS];
    __shared__ float  le[NCLS];
    __shared__ unsigned int s_ticket;
    const int tid  = threadIdx.x;
    const int lane = tid & 31;
    const int wid  = tid >> 5;
    const ull ones = PACKED_ONES;

    ull acc[NCLS];
    #pragma unroll
    for (int c = 0; c < NCLS; c++) acc[c] = 0ull;

    const int n4 = n >> 2;
    const float4* __restrict__ o4 = reinterpret_cast<const float4*>(outs);
    const float4* __restrict__ t4 = reinterpret_cast<const float4*>(tgts);
    const int4*   __restrict__ m4 = reinterpret_cast<const int4*>(mask);

    const int stride = NGRID * BLOCK;
    int i = blockIdx.x * BLOCK + tid;

    // unroll x3: 9 front-batched LDG.128 per iteration (deeper per-warp MLP)
    for (; i + 2 * stride < n4; i += 3 * stride) {
        float4 ov0 = o4[i];
        float4 ov1 = o4[i + stride];
        float4 ov2 = o4[i + 2 * stride];
        float4 tv0 = t4[i];
        float4 tv1 = t4[i + stride];
        float4 tv2 = t4[i + 2 * stride];
        int4   mv0 = m4[i];
        int4   mv1 = m4[i + stride];
        int4   mv2 = m4[i + 2 * stride];
        acc_el(ov0.x, tv0.x, mv0.x, acc, ones);
        acc_el(ov0.y, tv0.y, mv0.y, acc, ones);
        acc_el(ov0.z, tv0.z, mv0.z, acc, ones);
        acc_el(ov0.w, tv0.w, mv0.w, acc, ones);
        acc_el(ov1.x, tv1.x, mv1.x, acc, ones);
        acc_el(ov1.y, tv1.y, mv1.y, acc, ones);
        acc_el(ov1.z, tv1.z, mv1.z, acc, ones);
        acc_el(ov1.w, tv1.w, mv1.w, acc, ones);
        acc_el(ov2.x, tv2.x, mv2.x, acc, ones);
        acc_el(ov2.y, tv2.y, mv2.y, acc, ones);
        acc_el(ov2.z, tv2.z, mv2.z, acc, ones);
        acc_el(ov2.w, tv2.w, mv2.w, acc, ones);
    }
    for (; i < n4; i += stride) {        // remainder float4s
        float4 ov = o4[i];
        float4 tv = t4[i];
        int4   mv = m4[i];
        acc_el(ov.x, tv.x, mv.x, acc, ones);
        acc_el(ov.y, tv.y, mv.y, acc, ones);
        acc_el(ov.z, tv.z, mv.z, acc, ones);
        acc_el(ov.w, tv.w, mv.w, acc, ones);
    }
    if (blockIdx.x == 0) {               // scalar tail (n % 4)
        int j = (n4 << 2) + tid;
        if (j < n) acc_el(outs[j], tgts[j], mask[j], acc, ones);
    }

    // ---- warp shuffle reduction (float2 packed in ull) ----
    #pragma unroll
    for (int off = 16; off > 0; off >>= 1) {
        #pragma unroll
        for (int c = 0; c < NCLS; c++) {
            ull other = __shfl_down_sync(0xffffffffu, acc[c], off);
            asm("fma.rn.f32x2 %0, %1, %2, %0;" : "+l"(acc[c]) : "l"(other), "l"(ones));
        }
    }
    if (lane == 0) {
        #pragma unroll
        for (int c = 0; c < NCLS; c++) {
            float2 v;
            asm("mov.b64 {%0, %1}, %2;" : "=f"(v.x), "=f"(v.y) : "l"(acc[c]));
            s_warp[wid][c] = v;
        }
    }
    __syncthreads();

    if (tid < NCLS) {
        float2 p = make_float2(0.0f, 0.0f);
        #pragma unroll
        for (int w = 0; w < NWARPS; w++) {
            float2 v = s_warp[w][tid];
            p.x += v.x; p.y += v.y;
        }
        g_part[blockIdx.x][tid] = p;
    }
    __threadfence();
    __syncthreads();
    if (tid == 0) s_ticket = atomicAdd(&g_ticket, 1u);
    __syncthreads();
    if (s_ticket != (unsigned)(gridDim.x - 1)) return;

    // ---- last block: reduce partials, finalize, write output ----
    __threadfence();

    float2 racc[NCLS];
    #pragma unroll
    for (int c = 0; c < NCLS; c++) racc[c] = make_float2(0.0f, 0.0f);
    for (int j = tid; j < NGRID; j += BLOCK) {
        #pragma unroll
        for (int c = 0; c < NCLS; c++) {
            float2 p = g_part[j][c];
            racc[c].x += p.x;
            racc[c].y += p.y;
        }
    }
    #pragma unroll
    for (int off = 16; off > 0; off >>= 1) {
        #pragma unroll
        for (int c = 0; c < NCLS; c++) {
            racc[c].x += __shfl_down_sync(0xffffffffu, racc[c].x, off);
            racc[c].y += __shfl_down_sync(0xffffffffu, racc[c].y, off);
        }
    }
    if (lane == 0) {
        #pragma unroll
        for (int c = 0; c < NCLS; c++) s_warp[wid][c] = racc[c];
    }
    __syncthreads();

    if (tid < NCLS) {
        float2 tot = make_float2(0.0f, 0.0f);
        #pragma unroll
        for (int w = 0; w < NWARPS; w++) {
            float2 v = s_warp[w][tid];
            tot.x += v.x; tot.y += v.y;
        }
        s_warp[0][tid] = tot;
        le[tid] = (tot.y > 0.0f) ? (tot.x / fmaxf(tot.y, 1.0f)) : 0.0f;
    }
    __syncthreads();

    if (tid == 0) {
        float loss = 0.0f;
        #pragma unroll
        for (int c = 0; c < NCLS; c++) loss += 0.1f * le[c];
        out[0] = loss;
        g_ticket = 0;
    } else if (tid >= 1 && tid <= NCLS) {
        out[tid] = le[tid - 1];                  // loss_each
    } else if (tid >= NCLS + 1 && tid <= 2 * NCLS) {
        out[tid] = s_warp[0][tid - NCLS - 1].y;  // class_n
    } else if (tid < out_size) {
        out[tid] = 0.0f;
    }
}

extern "C" void kernel_launch(void* const* d_in, const int* in_sizes, int n_in,
                              void* d_out, int out_size) {
    const float* outs = (const float*)d_in[0];
    const float* tgts = (const float*)d_in[1];
    const int*   mask = (const int*)d_in[2];
    float* out = (float*)d_out;
    int n = in_sizes[0];

    loss_k<<<NGRID, BLOCK>>>(outs, tgts, mask, n, out, out_size);
}

// round 11
// speedup vs baseline: 1.0063x; 1.0056x over previous
#include <cuda_runtime.h>
#include <cstdint>

#define NCLS   10
#define BLOCK  256
#define NGRID  (152 * 4)     // 4 blocks/SM -> exactly one wave
#define NWARPS (BLOCK / 32)

typedef unsigned long long ull;

__device__ float2       g_part[NGRID][NCLS];
__device__ unsigned int g_ticket = 0;

#define PACKED_ONES 0x3F8000003F800000ull   // {1.0f, 1.0f}

// Four elements -> 10 register accumulators, ONE asm block:
// accumulator operands bound once per float4 (4x fewer asm-boundary bindings).
// Per element: pv = (m==1); inc = {sq, 1.0};
// per class:   p = (t==c) && pv;  @p acc[c] += inc * {1,1}  (FFMA2)
__device__ __forceinline__ void acc4(const float4& o, const float4& t,
                                     const int4& m, ull* a, ull ones) {
    float e0 = o.x - t.x, e1 = o.y - t.y, e2 = o.z - t.z, e3 = o.w - t.w;
    float s0 = e0 * e0, s1 = e1 * e1, s2 = e2 * e2, s3 = e3 * e3;
    asm volatile(
        "{\n\t"
        ".reg .pred pv0, pv1, pv2, pv3, p;\n\t"
        ".reg .b64  i0, i1, i2, i3;\n\t"
        ".reg .f32  fone;\n\t"
        "mov.f32 fone, 0F3F800000;\n\t"
        "setp.eq.s32 pv0, %18, 1;\n\t"
        "setp.eq.s32 pv1, %19, 1;\n\t"
        "setp.eq.s32 pv2, %20, 1;\n\t"
        "setp.eq.s32 pv3, %21, 1;\n\t"
        "mov.b64 i0, {%14, fone};\n\t"
        "mov.b64 i1, {%15, fone};\n\t"
        "mov.b64 i2, {%16, fone};\n\t"
        "mov.b64 i3, {%17, fone};\n\t"
        // element 0
        "setp.eq.and.f32 p, %10, 0F00000000, pv0;\n\t @p fma.rn.f32x2 %0, i0, %22, %0;\n\t"
        "setp.eq.and.f32 p, %10, 0F3F800000, pv0;\n\t @p fma.rn.f32x2 %1, i0, %22, %1;\n\t"
        "setp.eq.and.f32 p, %10, 0F40000000, pv0;\n\t @p fma.rn.f32x2 %2, i0, %22, %2;\n\t"
        "setp.eq.and.f32 p, %10, 0F40400000, pv0;\n\t @p fma.rn.f32x2 %3, i0, %22, %3;\n\t"
        "setp.eq.and.f32 p, %10, 0F40800000, pv0;\n\t @p fma.rn.f32x2 %4, i0, %22, %4;\n\t"
        "setp.eq.and.f32 p, %10, 0F40A00000, pv0;\n\t @p fma.rn.f32x2 %5, i0, %22, %5;\n\t"
        "setp.eq.and.f32 p, %10, 0F40C00000, pv0;\n\t @p fma.rn.f32x2 %6, i0, %22, %6;\n\t"
        "setp.eq.and.f32 p, %10, 0F40E00000, pv0;\n\t @p fma.rn.f32x2 %7, i0, %22, %7;\n\t"
        "setp.eq.and.f32 p, %10, 0F41000000, pv0;\n\t @p fma.rn.f32x2 %8, i0, %22, %8;\n\t"
        "setp.eq.and.f32 p, %10, 0F41100000, pv0;\n\t @p fma.rn.f32x2 %9, i0, %22, %9;\n\t"
        // element 1
        "setp.eq.and.f32 p, %11, 0F00000000, pv1;\n\t @p fma.rn.f32x2 %0, i1, %22, %0;\n\t"
        "setp.eq.and.f32 p, %11, 0F3F800000, pv1;\n\t @p fma.rn.f32x2 %1, i1, %22, %1;\n\t"
        "setp.eq.and.f32 p, %11, 0F40000000, pv1;\n\t @p fma.rn.f32x2 %2, i1, %22, %2;\n\t"
        "setp.eq.and.f32 p, %11, 0F40400000, pv1;\n\t @p fma.rn.f32x2 %3, i1, %22, %3;\n\t"
        "setp.eq.and.f32 p, %11, 0F40800000, pv1;\n\t @p fma.rn.f32x2 %4, i1, %22, %4;\n\t"
        "setp.eq.and.f32 p, %11, 0F40A00000, pv1;\n\t @p fma.rn.f32x2 %5, i1, %22, %5;\n\t"
        "setp.eq.and.f32 p, %11, 0F40C00000, pv1;\n\t @p fma.rn.f32x2 %6, i1, %22, %6;\n\t"
        "setp.eq.and.f32 p, %11, 0F40E00000, pv1;\n\t @p fma.rn.f32x2 %7, i1, %22, %7;\n\t"
        "setp.eq.and.f32 p, %11, 0F41000000, pv1;\n\t @p fma.rn.f32x2 %8, i1, %22, %8;\n\t"
        "setp.eq.and.f32 p, %11, 0F41100000, pv1;\n\t @p fma.rn.f32x2 %9, i1, %22, %9;\n\t"
        // element 2
        "setp.eq.and.f32 p, %12, 0F00000000, pv2;\n\t @p fma.rn.f32x2 %0, i2, %22, %0;\n\t"
        "setp.eq.and.f32 p, %12, 0F3F800000, pv2;\n\t @p fma.rn.f32x2 %1, i2, %22, %1;\n\t"
        "setp.eq.and.f32 p, %12, 0F40000000, pv2;\n\t @p fma.rn.f32x2 %2, i2, %22, %2;\n\t"
        "setp.eq.and.f32 p, %12, 0F40400000, pv2;\n\t @p fma.rn.f32x2 %3, i2, %22, %3;\n\t"
        "setp.eq.and.f32 p, %12, 0F40800000, pv2;\n\t @p fma.rn.f32x2 %4, i2, %22, %4;\n\t"
        "setp.eq.and.f32 p, %12, 0F40A00000, pv2;\n\t @p fma.rn.f32x2 %5, i2, %22, %5;\n\t"
        "setp.eq.and.f32 p, %12, 0F40C00000, pv2;\n\t @p fma.rn.f32x2 %6, i2, %22, %6;\n\t"
        "setp.eq.and.f32 p, %12, 0F40E00000, pv2;\n\t @p fma.rn.f32x2 %7, i2, %22, %7;\n\t"
        "setp.eq.and.f32 p, %12, 0F41000000, pv2;\n\t @p fma.rn.f32x2 %8, i2, %22, %8;\n\t"
        "setp.eq.and.f32 p, %12, 0F41100000, pv2;\n\t @p fma.rn.f32x2 %9, i2, %22, %9;\n\t"
        // element 3
        "setp.eq.and.f32 p, %13, 0F00000000, pv3;\n\t @p fma.rn.f32x2 %0, i3, %22, %0;\n\t"
        "setp.eq.and.f32 p, %13, 0F3F800000, pv3;\n\t @p fma.rn.f32x2 %1, i3, %22, %1;\n\t"
        "setp.eq.and.f32 p, %13, 0F40000000, pv3;\n\t @p fma.rn.f32x2 %2, i3, %22, %2;\n\t"
        "setp.eq.and.f32 p, %13, 0F40400000, pv3;\n\t @p fma.rn.f32x2 %3, i3, %22, %3;\n\t"
        "setp.eq.and.f32 p, %13, 0F40800000, pv3;\n\t @p fma.rn.f32x2 %4, i3, %22, %4;\n\t"
        "setp.eq.and.f32 p, %13, 0F40A00000, pv3;\n\t @p fma.rn.f32x2 %5, i3, %22, %5;\n\t"
        "setp.eq.and.f32 p, %13, 0F40C00000, pv3;\n\t @p fma.rn.f32x2 %6, i3, %22, %6;\n\t"
        "setp.eq.and.f32 p, %13, 0F40E00000, pv3;\n\t @p fma.rn.f32x2 %7, i3, %22, %7;\n\t"
        "setp.eq.and.f32 p, %13, 0F41000000, pv3;\n\t @p fma.rn.f32x2 %8, i3, %22, %8;\n\t"
        "setp.eq.and.f32 p, %13, 0F41100000, pv3;\n\t @p fma.rn.f32x2 %9, i3, %22, %9;\n\t"
        "}"
        : "+l"(a[0]), "+l"(a[1]), "+l"(a[2]), "+l"(a[3]), "+l"(a[4]),
          "+l"(a[5]), "+l"(a[6]), "+l"(a[7]), "+l"(a[8]), "+l"(a[9])
        : "f"(t.x), "f"(t.y), "f"(t.z), "f"(t.w),
          "f"(s0), "f"(s1), "f"(s2), "f"(s3),
          "r"(m.x), "r"(m.y), "r"(m.z), "r"(m.w),
          "l"(ones));
}

// scalar fallback for the tail
__device__ __forceinline__ void acc1(float o, float t, int m, ull* a, ull ones) {
    float e = o - t;
    float sq = e * e;
    bool v = (m == 1);
    float sqv = v ? sq : 0.0f;
    float onev = v ? 1.0f : 0.0f;
    ull inc;
    asm("mov.b64 %0, {%1, %2};" : "=l"(inc) : "f"(sqv), "f"(onev));
    #pragma unroll
    for (int c = 0; c < NCLS; c++) {
        float cf = (float)c;
        ull r = a[c];
        asm("{ .reg .pred p; setp.eq.f32 p, %1, %2;\n\t"
            "@p fma.rn.f32x2 %0, %3, %4, %0; }"
            : "+l"(r) : "f"(t), "f"(cf), "l"(inc), "l"(ones));
        a[c] = r;
    }
}

__global__ __launch_bounds__(BLOCK, 4) void loss_k(
    const float* __restrict__ outs,
    const float* __restrict__ tgts,
    const int*   __restrict__ mask,
    int n, float* __restrict__ out, int out_size)
{
    __shared__ float2 s_warp[NWARPS][NCLS];
    __shared__ float  le[NCLS];
    __shared__ unsigned int s_ticket;
    const int tid  = threadIdx.x;
    const int lane = tid & 31;
    const int wid  = tid >> 5;
    const ull ones = PACKED_ONES;

    ull acc[NCLS];
    #pragma unroll
    for (int c = 0; c < NCLS; c++) acc[c] = 0ull;

    const int n4 = n >> 2;
    const float4* __restrict__ o4 = reinterpret_cast<const float4*>(outs);
    const float4* __restrict__ t4 = reinterpret_cast<const float4*>(tgts);
    const int4*   __restrict__ m4 = reinterpret_cast<const int4*>(mask);

    const int stride = NGRID * BLOCK;
    int i = blockIdx.x * BLOCK + tid;

    // unroll x2: 6 front-batched LDG.128 per iteration
    for (; i + stride < n4; i += 2 * stride) {
        float4 ov0 = o4[i];
        float4 ov1 = o4[i + stride];
        float4 tv0 = t4[i];
        float4 tv1 = t4[i + stride];
        int4   mv0 = m4[i];
        int4   mv1 = m4[i + stride];
        acc4(ov0, tv0, mv0, acc, ones);
        acc4(ov1, tv1, mv1, acc, ones);
    }
    if (i < n4) {
        float4 ov = o4[i];
        float4 tv = t4[i];
        int4   mv = m4[i];
        acc4(ov, tv, mv, acc, ones);
    }
    if (blockIdx.x == 0) {               // scalar tail (n % 4)
        int j = (n4 << 2) + tid;
        if (j < n) acc1(outs[j], tgts[j], mask[j], acc, ones);
    }

    // ---- warp shuffle reduction (float2 packed in ull) ----
    #pragma unroll
    for (int off = 16; off > 0; off >>= 1) {
        #pragma unroll
        for (int c = 0; c < NCLS; c++) {
            ull other = __shfl_down_sync(0xffffffffu, acc[c], off);
            asm("fma.rn.f32x2 %0, %1, %2, %0;" : "+l"(acc[c]) : "l"(other), "l"(ones));
        }
    }
    if (lane == 0) {
        #pragma unroll
        for (int c = 0; c < NCLS; c++) {
            float2 v;
            asm("mov.b64 {%0, %1}, %2;" : "=f"(v.x), "=f"(v.y) : "l"(acc[c]));
            s_warp[wid][c] = v;
        }
    }
    __syncthreads();

    if (tid < NCLS) {
        float2 p = make_float2(0.0f, 0.0f);
        #pragma unroll
        for (int w = 0; w < NWARPS; w++) {
            float2 v = s_warp[w][tid];
            p.x += v.x; p.y += v.y;
        }
        g_part[blockIdx.x][tid] = p;
    }
    __threadfence();
    __syncthreads();
    if (tid == 0) s_ticket = atomicAdd(&g_ticket, 1u);
    __syncthreads();
    if (s_ticket != (unsigned)(gridDim.x - 1)) return;

    // ---- last block: reduce partials, finalize, write output ----
    __threadfence();

    float2 racc[NCLS];
    #pragma unroll
    for (int c = 0; c < NCLS; c++) racc[c] = make_float2(0.0f, 0.0f);
    for (int j = tid; j < NGRID; j += BLOCK) {
        #pragma unroll
        for (int c = 0; c < NCLS; c++) {
            float2 p = g_part[j][c];
            racc[c].x += p.x;
            racc[c].y += p.y;
        }
    }
    #pragma unroll
    for (int off = 16; off > 0; off >>= 1) {
        #pragma unroll
        for (int c = 0; c < NCLS; c++) {
            racc[c].x += __shfl_down_sync(0xffffffffu, racc[c].x, off);
            racc[c].y += __shfl_down_sync(0xffffffffu, racc[c].y, off);
        }
    }
    if (lane == 0) {
        #pragma unroll
        for (int c = 0; c < NCLS; c++) s_warp[wid][c] = racc[c];
    }
    __syncthreads();

    if (tid < NCLS) {
        float2 tot = make_float2(0.0f, 0.0f);
        #pragma unroll
        for (int w = 0; w < NWARPS; w++) {
            float2 v = s_warp[w][tid];
            tot.x += v.x; tot.y += v.y;
        }
        s_warp[0][tid] = tot;
        le[tid] = (tot.y > 0.0f) ? (tot.x / fmaxf(tot.y, 1.0f)) : 0.0f;
    }
    __syncthreads();

    if (tid == 0) {
        float loss = 0.0f;
        #pragma unroll
        for (int c = 0; c < NCLS; c++) loss += 0.1f * le[c];
        out[0] = loss;
        g_ticket = 0;
    } else if (tid >= 1 && tid <= NCLS) {
        out[tid] = le[tid - 1];                  // loss_each
    } else if (tid >= NCLS + 1 && tid <= 2 * NCLS) {
        out[tid] = s_warp[0][tid - NCLS - 1].y;  // class_n
    } else if (tid < out_size) {
        out[tid] = 0.0f;
    }
}

extern "C" void kernel_launch(void* const* d_in, const int* in_sizes, int n_in,
                              void* d_out, int out_size) {
    const float* outs = (const float*)d_in[0];
    const float* tgts = (const float*)d_in[1];
    const int*   mask = (const int*)d_in[2];
    float* out = (float*)d_out;
    int n = in_sizes[0];

    loss_k<<<NGRID, BLOCK>>>(outs, tgts, mask, n, out, out_size);
}

// round 13
// speedup vs baseline: 1.1633x; 1.1560x over previous
#include <cuda_runtime.h>
#include <cstdint>

#define NCLS   10
#define BLOCK  256
#define NGRID  (152 * 4)     // 4 blocks/SM -> exactly one wave
#define NWARPS (BLOCK / 32)

__device__ float2       g_part[NGRID][NCLS];
__device__ unsigned int g_ticket = 0;

// One element -> 10 (sum, cnt) scalar accumulator pairs, UN-predicated:
//   ind  = (tq == c) ? 1.0f : 0.0f        (FSET, single SASS)
//   sum += ind * sq                        (FFMA)
//   cnt += ind                             (FADD)
// Invalid pixels: tq = 1e30f never matches any class.
__device__ __forceinline__ void acc_el(float o, float t, int m,
                                       float* s, float* cn) {
    float e  = o - t;
    float sq = e * e;
    float tq = (m == 1) ? t : 1e30f;
    #pragma unroll
    for (int c = 0; c < NCLS; c++) {
        float ind;
        asm("set.eq.f32.f32 %0, %1, %2;" : "=f"(ind) : "f"(tq), "f"((float)c));
        s[c]  = fmaf(ind, sq, s[c]);
        cn[c] += ind;
    }
}

__global__ __launch_bounds__(BLOCK, 4) void loss_k(
    const float* __restrict__ outs,
    const float* __restrict__ tgts,
    const int*   __restrict__ mask,
    int n, float* __restrict__ out, int out_size)
{
    __shared__ float2 s_warp[NWARPS][NCLS];
    __shared__ float  le[NCLS];
    __shared__ unsigned int s_ticket;
    const int tid  = threadIdx.x;
    const int lane = tid & 31;
    const int wid  = tid >> 5;

    float s[NCLS], cn[NCLS];
    #pragma unroll
    for (int c = 0; c < NCLS; c++) { s[c] = 0.0f; cn[c] = 0.0f; }

    const int n4 = n >> 2;
    const float4* __restrict__ o4 = reinterpret_cast<const float4*>(outs);
    const float4* __restrict__ t4 = reinterpret_cast<const float4*>(tgts);
    const int4*   __restrict__ m4 = reinterpret_cast<const int4*>(mask);

    const int stride = NGRID * BLOCK;
    int i = blockIdx.x * BLOCK + tid;

    // unroll x2: 6 front-batched LDG.128 per iteration
    for (; i + stride < n4; i += 2 * stride) {
        float4 ov0 = o4[i];
        float4 ov1 = o4[i + stride];
        float4 tv0 = t4[i];
        float4 tv1 = t4[i + stride];
        int4   mv0 = m4[i];
        int4   mv1 = m4[i + stride];
        acc_el(ov0.x, tv0.x, mv0.x, s, cn);
        acc_el(ov0.y, tv0.y, mv0.y, s, cn);
        acc_el(ov0.z, tv0.z, mv0.z, s, cn);
        acc_el(ov0.w, tv0.w, mv0.w, s, cn);
        acc_el(ov1.x, tv1.x, mv1.x, s, cn);
        acc_el(ov1.y, tv1.y, mv1.y, s, cn);
        acc_el(ov1.z, tv1.z, mv1.z, s, cn);
        acc_el(ov1.w, tv1.w, mv1.w, s, cn);
    }
    if (i < n4) {
        float4 ov = o4[i];
        float4 tv = t4[i];
        int4   mv = m4[i];
        acc_el(ov.x, tv.x, mv.x, s, cn);
        acc_el(ov.y, tv.y, mv.y, s, cn);
        acc_el(ov.z, tv.z, mv.z, s, cn);
        acc_el(ov.w, tv.w, mv.w, s, cn);
    }
    if (blockIdx.x == 0) {               // scalar tail (n % 4)
        int j = (n4 << 2) + tid;
        if (j < n) acc_el(outs[j], tgts[j], mask[j], s, cn);
    }

    // ---- warp shuffle reduction ----
    #pragma unroll
    for (int off = 16; off > 0; off >>= 1) {
        #pragma unroll
        for (int c = 0; c < NCLS; c++) {
            s[c]  += __shfl_down_sync(0xffffffffu, s[c],  off);
            cn[c] += __shfl_down_sync(0xffffffffu, cn[c], off);
        }
    }
    if (lane == 0) {
        #pragma unroll
        for (int c = 0; c < NCLS; c++) s_warp[wid][c] = make_float2(s[c], cn[c]);
    }
    __syncthreads();

    // ---- per-block partial: threads 0..9 combine the warp rows ----
    if (tid < NCLS) {
        float2 p = make_float2(0.0f, 0.0f);
        #pragma unroll
        for (int w = 0; w < NWARPS; w++) {
            float2 v = s_warp[w][tid];
            p.x += v.x; p.y += v.y;
        }
        g_part[blockIdx.x][tid] = p;
    }
    __threadfence();
    __syncthreads();
    if (tid == 0) s_ticket = atomicAdd(&g_ticket, 1u);
    __syncthreads();
    if (s_ticket != (unsigned)(gridDim.x - 1)) return;

    // ---- last block: reduce partials, finalize, write output ----
    __threadfence();

    float2 racc[NCLS];
    #pragma unroll
    for (int c = 0; c < NCLS; c++) racc[c] = make_float2(0.0f, 0.0f);
    for (int j = tid; j < NGRID; j += BLOCK) {
        #pragma unroll
        for (int c = 0; c < NCLS; c++) {
            float2 p = g_part[j][c];
            racc[c].x += p.x;
            racc[c].y += p.y;
        }
    }
    #pragma unroll
    for (int off = 16; off > 0; off >>= 1) {
        #pragma unroll
        for (int c = 0; c < NCLS; c++) {
            racc[c].x += __shfl_down_sync(0xffffffffu, racc[c].x, off);
            racc[c].y += __shfl_down_sync(0xffffffffu, racc[c].y, off);
        }
    }
    if (lane == 0) {
        #pragma unroll
        for (int c = 0; c < NCLS; c++) s_warp[wid][c] = racc[c];
    }
    __syncthreads();

    if (tid < NCLS) {
        float2 tot = make_float2(0.0f, 0.0f);
        #pragma unroll
        for (int w = 0; w < NWARPS; w++) {
            float2 v = s_warp[w][tid];
            tot.x += v.x; tot.y += v.y;
        }
        s_warp[0][tid] = tot;
        le[tid] = (tot.y > 0.0f) ? (tot.x / fmaxf(tot.y, 1.0f)) : 0.0f;
    }
    __syncthreads();

    if (tid == 0) {
        float loss = 0.0f;
        #pragma unroll
        for (int c = 0; c < NCLS; c++) loss += 0.1f * le[c];
        out[0] = loss;
        g_ticket = 0;    // reset for graph replay determinism
    } else if (tid >= 1 && tid <= NCLS) {
        out[tid] = le[tid - 1];                  // loss_each
    } else if (tid >= NCLS + 1 && tid <= 2 * NCLS) {
        out[tid] = s_warp[0][tid - NCLS - 1].y;  // class_n
    } else if (tid < out_size) {
        out[tid] = 0.0f;
    }
}

extern "C" void kernel_launch(void* const* d_in, const int* in_sizes, int n_in,
                              void* d_out, int out_size) {
    const float* outs = (const float*)d_in[0];
    const float* tgts = (const float*)d_in[1];
    const int*   mask = (const int*)d_in[2];
    float* out = (float*)d_out;
    int n = in_sizes[0];

    loss_k<<<NGRID, BLOCK>>>(outs, tgts, mask, n, out, out_size);
}